// round 13
// baseline (speedup 1.0000x reference)
#include <cuda_runtime.h>

#define LSEQ   2048
#define NBATCH 2
#define NHEADS 16
#define DMODEL 1024

// Scratch for attention output before the fc GEMM (16.8 MB).
__device__ float g_attn[(size_t)NBATCH * LSEQ * DMODEL];

__device__ __forceinline__ unsigned f2t(float x) {
    unsigned r;
    asm("cvt.rna.tf32.f32 %0, %1;" : "=r"(r) : "f"(x));
    return r;
}

__device__ __forceinline__ void mma8(float* c, const unsigned* a, const unsigned* b) {
    asm volatile(
        "mma.sync.aligned.m16n8k8.row.col.f32.tf32.tf32.f32 "
        "{%0,%1,%2,%3}, {%4,%5,%6,%7}, {%8,%9}, {%0,%1,%2,%3};"
        : "+f"(c[0]), "+f"(c[1]), "+f"(c[2]), "+f"(c[3])
        : "r"(a[0]), "r"(a[1]), "r"(a[2]), "r"(a[3]), "r"(b[0]), "r"(b[1]));
}

// ---------------------------------------------------------------------------
// Kernel 1: flash attention, tf32, fragment-major smem.
// Kf[j*8+s][lane^sw][2] = {K[8j+gid][8s+tig], K[8j+gid][8s+tig+4]}  (b-frag of QK)
// Vf[s*8+j][lane^sw][2] = {V[8s+tig][8j+gid], V[8s+tig+4][8j+gid]}  (b-frag of PV)
// One LDS.64 per b-frag in the mainloop. sw = idx&7 keeps fills ~2-way.
// ---------------------------------------------------------------------------
__global__ __launch_bounds__(128) void attn_kernel(
    const float* __restrict__ Q, const float* __restrict__ K,
    const float* __restrict__ V, const int* __restrict__ mask)
{
    __shared__ __align__(16) unsigned Kf[4096];   // 16 KB
    __shared__ __align__(16) unsigned Vf[4096];   // 16 KB
    __shared__ int Ms[64];

    const int tid  = threadIdx.x;
    const int w    = tid >> 5;
    const int lane = tid & 31;
    const int gid  = lane >> 2;   // 0..7
    const int tig  = lane & 3;    // 0..3
    const int odd  = tig & 1;
    const int src1 = (lane & 28) | (tig >> 1);
    const int src2 = src1 + 2;

    const int n = blockIdx.z, h = blockIdx.y;
    const int q0 = blockIdx.x * 64;

    const float* Qg = Q + ((size_t)n * LSEQ) * DMODEL + h * 64;
    const float* Kg = K + ((size_t)n * LSEQ) * DMODEL + h * 64;
    const float* Vg = V + ((size_t)n * LSEQ) * DMODEL + h * 64;
    const int*   Mg = mask + n * LSEQ;

    const int r_lo = 16 * w + gid;
    const int r_hi = r_lo + 8;

    // Q A-fragments in registers: 8 k-steps x 4 regs
    unsigned qa[8][4];
    {
        const float* q0p = Qg + (size_t)(q0 + r_lo) * DMODEL;
        const float* q1p = q0p + 8 * DMODEL;
        #pragma unroll
        for (int s = 0; s < 8; s++) {
            qa[s][0] = f2t(q0p[8 * s + tig]);
            qa[s][1] = f2t(q1p[8 * s + tig]);
            qa[s][2] = f2t(q0p[8 * s + tig + 4]);
            qa[s][3] = f2t(q1p[8 * s + tig + 4]);
        }
    }

    float Oc[8][4];
    #pragma unroll
    for (int j = 0; j < 8; j++)
        #pragma unroll
        for (int r = 0; r < 4; r++) Oc[j][r] = 0.f;

    float l_lo = 0.f, l_hi = 0.f;
    const float scale = 0.03125f;   // 1/sqrt(1024)

    for (int k0 = 0; k0 < LSEQ; k0 += 64) {
        __syncthreads();

        // Fill Kf/Vf in fragment-major order from coalesced float4 loads.
        #pragma unroll
        for (int i = 0; i < 8; i++) {
            const int f = tid * 4 + i * 512;
            const int r = f >> 6, c0 = f & 63;
            float4 kv = *(const float4*)(Kg + (size_t)(k0 + r) * DMODEL + c0);
            {
                const int j8s  = ((r >> 3) << 3) | (c0 >> 3);
                const int kreg = (c0 >> 2) & 1;
                const int kb   = (j8s << 6) + kreg;
                const int lb   = (r & 7) << 2;           // lane base = 4*gid
                const int sw   = j8s & 7;
                Kf[kb + (((lb + 0) ^ sw) << 1)] = f2t(kv.x);
                Kf[kb + (((lb + 1) ^ sw) << 1)] = f2t(kv.y);
                Kf[kb + (((lb + 2) ^ sw) << 1)] = f2t(kv.z);
                Kf[kb + (((lb + 3) ^ sw) << 1)] = f2t(kv.w);
            }
            float4 vv = *(const float4*)(Vg + (size_t)(k0 + r) * DMODEL + c0);
            {
                const int s    = r >> 3, rr = r & 7;
                const int vtig = rr & 3, vreg = rr >> 2;
                const int s8j  = (s << 3) | (c0 >> 3);
                const int vb   = (s8j << 6) + vreg;
                const int g0   = c0 & 7;                 // gid of element 0
                const int sw   = s8j & 7;
                Vf[vb + ((((g0 + 0) * 4 + vtig) ^ sw) << 1)] = f2t(vv.x);
                Vf[vb + ((((g0 + 1) * 4 + vtig) ^ sw) << 1)] = f2t(vv.y);
                Vf[vb + ((((g0 + 2) * 4 + vtig) ^ sw) << 1)] = f2t(vv.z);
                Vf[vb + ((((g0 + 3) * 4 + vtig) ^ sw) << 1)] = f2t(vv.w);
            }
        }
        if (tid < 64) Ms[tid] = Mg[k0 + tid];
        __syncthreads();

        // S = Q K^T : b-frag = one LDS.64
        float Sc[8][4];
        #pragma unroll
        for (int j = 0; j < 8; j++)
            #pragma unroll
            for (int r = 0; r < 4; r++) Sc[j][r] = 0.f;

        #pragma unroll
        for (int s = 0; s < 8; s++) {
            #pragma unroll
            for (int j = 0; j < 8; j++) {
                const int idx = j * 8 + s;
                const uint2 b = *(const uint2*)&Kf[(idx << 6) + ((lane ^ (idx & 7)) << 1)];
                mma8(Sc[j], qa[s], (const unsigned*)&b);
            }
        }

        // P = exp(scale * S), masked -> 0 (fixed-max softmax, exact).
        #pragma unroll
        for (int j = 0; j < 8; j++) {
            const int mk0 = Ms[8 * j + 2 * tig];
            const int mk1 = Ms[8 * j + 2 * tig + 1];
            const float p0 = mk0 ? __expf(Sc[j][0] * scale) : 0.f;
            const float p1 = mk1 ? __expf(Sc[j][1] * scale) : 0.f;
            const float p2 = mk0 ? __expf(Sc[j][2] * scale) : 0.f;
            const float p3 = mk1 ? __expf(Sc[j][3] * scale) : 0.f;
            Sc[j][0] = p0; Sc[j][1] = p1; Sc[j][2] = p2; Sc[j][3] = p3;
            l_lo += p0 + p1;
            l_hi += p2 + p3;
        }

        // O += P V : P permuted C->A layout via quad shuffles; V b-frag = LDS.64.
        #pragma unroll
        for (int s = 0; s < 8; s++) {
            const float x0 = __shfl_sync(0xffffffffu, Sc[s][0], src1);
            const float x1 = __shfl_sync(0xffffffffu, Sc[s][1], src1);
            const float x2 = __shfl_sync(0xffffffffu, Sc[s][2], src1);
            const float x3 = __shfl_sync(0xffffffffu, Sc[s][3], src1);
            const float y0 = __shfl_sync(0xffffffffu, Sc[s][0], src2);
            const float y1 = __shfl_sync(0xffffffffu, Sc[s][1], src2);
            const float y2 = __shfl_sync(0xffffffffu, Sc[s][2], src2);
            const float y3 = __shfl_sync(0xffffffffu, Sc[s][3], src2);
            unsigned pa[4];
            pa[0] = f2t(odd ? x1 : x0);
            pa[1] = f2t(odd ? x3 : x2);
            pa[2] = f2t(odd ? y1 : y0);
            pa[3] = f2t(odd ? y3 : y2);
            #pragma unroll
            for (int j = 0; j < 8; j++) {
                const int idx = s * 8 + j;
                const uint2 b = *(const uint2*)&Vf[(idx << 6) + ((lane ^ (idx & 7)) << 1)];
                mma8(Oc[j], pa, (const unsigned*)&b);
            }
        }
    }

    #pragma unroll
    for (int o = 1; o <= 2; o <<= 1) {
        l_lo += __shfl_xor_sync(0xffffffffu, l_lo, o);
        l_hi += __shfl_xor_sync(0xffffffffu, l_hi, o);
    }
    const float inv_lo = 1.f / l_lo;
    const float inv_hi = 1.f / l_hi;

    float* Og = g_attn + ((size_t)n * LSEQ) * DMODEL + h * 64;
    #pragma unroll
    for (int j = 0; j < 8; j++) {
        const int c = 8 * j + 2 * tig;
        float2 v0 = make_float2(Oc[j][0] * inv_lo, Oc[j][1] * inv_lo);
        float2 v1 = make_float2(Oc[j][2] * inv_hi, Oc[j][3] * inv_hi);
        *(float2*)(Og + (size_t)(q0 + r_lo) * DMODEL + c) = v0;
        *(float2*)(Og + (size_t)(q0 + r_hi) * DMODEL + c) = v1;
    }
}

// ---------------------------------------------------------------------------
// Kernel 2: out = g_attn @ fc_w^T + fc_b, fragment-major smem.
// Af[mb*4+ks8][lane^sw][4] : a-frag = one LDS.128
// Wf[nb*4+ks8][lane^sw][2] : b-frag = one LDS.64
// CTA tile 128x64, 256 threads = 8 warps (4 m x 2 n), 512 CTAs.
// ---------------------------------------------------------------------------
__global__ __launch_bounds__(256) void fc_kernel(
    const float* __restrict__ W, const float* __restrict__ bias,
    float* __restrict__ out)
{
    __shared__ __align__(16) unsigned Af[4096];   // 16 KB
    __shared__ __align__(16) unsigned Wf[2048];   //  8 KB

    const int tid  = threadIdx.x;
    const int w    = tid >> 5;
    const int lane = tid & 31;
    const int gid  = lane >> 2;
    const int tig  = lane & 3;
    const int wm = w >> 1;    // 0..3
    const int wn = w & 1;     // 0..1

    const int i0 = blockIdx.y * 128;
    const int o0 = blockIdx.x * 64;

    float acc[2][4][4];
    #pragma unroll
    for (int mt = 0; mt < 2; mt++)
        #pragma unroll
        for (int j = 0; j < 4; j++)
            #pragma unroll
            for (int r = 0; r < 4; r++) acc[mt][j][r] = 0.f;

    for (int kt = 0; kt < DMODEL; kt += 32) {
        __syncthreads();
        // A: 128x32 -> fragment-major (4 float4 per thread)
        #pragma unroll
        for (int i = 0; i < 4; i++) {
            const int f = tid * 4 + i * 1024;
            const int row = f >> 5, c0 = f & 31;
            float4 a = *(const float4*)(g_attn + (size_t)(i0 + row) * DMODEL + kt + c0);
            const int mb = row >> 4, rr = row & 15;
            const int hi = rr >> 3;
            const int half = (c0 >> 2) & 1;
            const int reg = half * 2 + hi;
            const int idx = (mb << 2) | (c0 >> 3);
            const int ab  = (idx << 7) + reg;
            const int lb  = (rr & 7) << 2;
            const int sw  = idx & 7;
            Af[ab + (((lb + 0) ^ sw) << 2)] = f2t(a.x);
            Af[ab + (((lb + 1) ^ sw) << 2)] = f2t(a.y);
            Af[ab + (((lb + 2) ^ sw) << 2)] = f2t(a.z);
            Af[ab + (((lb + 3) ^ sw) << 2)] = f2t(a.w);
        }
        // W: 64x32 -> fragment-major (2 float4 per thread)
        #pragma unroll
        for (int i = 0; i < 2; i++) {
            const int f = tid * 4 + i * 1024;
            const int o = f >> 5, c0 = f & 31;
            float4 wv = *(const float4*)(W + (size_t)(o0 + o) * DMODEL + kt + c0);
            const int reg = (c0 >> 2) & 1;
            const int idx = ((o >> 3) << 2) | (c0 >> 3);
            const int wb  = (idx << 6) + reg;
            const int lb  = (o & 7) << 2;
            const int sw  = idx & 7;
            Wf[wb + (((lb + 0) ^ sw) << 1)] = f2t(wv.x);
            Wf[wb + (((lb + 1) ^ sw) << 1)] = f2t(wv.y);
            Wf[wb + (((lb + 2) ^ sw) << 1)] = f2t(wv.z);
            Wf[wb + (((lb + 3) ^ sw) << 1)] = f2t(wv.w);
        }
        __syncthreads();

        #pragma unroll
        for (int ks8 = 0; ks8 < 4; ks8++) {
            uint4 av[2];
            uint2 bv[4];
            #pragma unroll
            for (int mt = 0; mt < 2; mt++) {
                const int idx = ((wm * 2 + mt) << 2) | ks8;
                av[mt] = *(const uint4*)&Af[(idx << 7) + ((lane ^ (idx & 7)) << 2)];
            }
            #pragma unroll
            for (int j = 0; j < 4; j++) {
                const int idx = ((wn * 4 + j) << 2) | ks8;
                bv[j] = *(const uint2*)&Wf[(idx << 6) + ((lane ^ (idx & 7)) << 1)];
            }
            #pragma unroll
            for (int mt = 0; mt < 2; mt++)
                #pragma unroll
                for (int j = 0; j < 4; j++)
                    mma8(acc[mt][j], (const unsigned*)&av[mt], (const unsigned*)&bv[j]);
        }
    }

    #pragma unroll
    for (int mt = 0; mt < 2; mt++) {
        const int r_lo = i0 + 32 * wm + 16 * mt + gid;
        const int r_hi = r_lo + 8;
        #pragma unroll
        for (int j = 0; j < 4; j++) {
            const int o = o0 + 32 * wn + 8 * j + 2 * tig;
            const float b0 = bias[o], b1 = bias[o + 1];
            float2 v0 = make_float2(acc[mt][j][0] + b0, acc[mt][j][1] + b1);
            float2 v1 = make_float2(acc[mt][j][2] + b0, acc[mt][j][3] + b1);
            *(float2*)(out + (size_t)r_lo * DMODEL + o) = v0;
            *(float2*)(out + (size_t)r_hi * DMODEL + o) = v1;
        }
    }
}

// ---------------------------------------------------------------------------
extern "C" void kernel_launch(void* const* d_in, const int* in_sizes, int n_in,
                              void* d_out, int out_size) {
    (void)in_sizes; (void)n_in; (void)out_size;
    const float* Q    = (const float*)d_in[0];
    const float* K    = (const float*)d_in[1];
    const float* V    = (const float*)d_in[2];
    const int*   mask = (const int*)d_in[3];
    const float* W    = (const float*)d_in[4];
    const float* b    = (const float*)d_in[5];
    float* out = (float*)d_out;

    attn_kernel<<<dim3(LSEQ / 64, NHEADS, NBATCH), 128>>>(Q, K, V, mask);
    fc_kernel<<<dim3(DMODEL / 64, (NBATCH * LSEQ) / 128), 256>>>(W, b, out);
}